// round 15
// baseline (speedup 1.0000x reference)
#include <cuda_runtime.h>
#include <math.h>

// Problem constants
#define NQ   64          // queries
#define DD   256         // feature dim
#define NS   4096        // bank size
#define IMG  65536       // C*H*W floats per image
#define FPB  32          // features per sim block
#define FBLOCKS (NS / FPB)   // 128

// smem layout for sim kernel (transposed, padded strides)
#define QS_STRIDE 68     // 64 rows + 4 pad (float4-aligned, conflict-free)
#define FS_STRIDE 36     // 32 rows + 4 pad
#define QS_FLOATS (DD * QS_STRIDE)   // 17408
#define FS_FLOATS (DD * FS_STRIDE)   //  9216
#define RED_SLOTS (NQ * 8)           // per-(query, warp) partials
#define SMEM_BYTES ((QS_FLOATS + FS_FLOATS) * 4 + RED_SLOTS * 8)  // 110592 B

// Per-(query, f-tile) partial argmax results. Every slot is rewritten on
// every replay -> no reset kernel, no atomics, fully deterministic.
__device__ unsigned long long g_part[NQ * FBLOCKS];

__device__ __forceinline__ unsigned long long packkey(float f, unsigned idx) {
    unsigned u = __float_as_uint(f);
    u = (u & 0x80000000u) ? ~u : (u | 0x80000000u);
    return ((unsigned long long)u << 32) | (0xFFFFFFFFu - idx);
}
__device__ __forceinline__ float unpackscore(unsigned long long p) {
    unsigned u = (unsigned)(p >> 32);
    unsigned bits = (u & 0x80000000u) ? (u & 0x7FFFFFFFu) : ~u;
    return __uint_as_float(bits);
}
__device__ __forceinline__ unsigned long long umax64(unsigned long long a,
                                                     unsigned long long b) {
    return a > b ? a : b;
}

// ---------------------------------------------------------------------------
// Kernel 1: sim tile GEMM (64 q x 32 f x K=256) on RAW q + fused argmax.
// (Measured-good R14 body; adds the PDL trigger after staging so the gather
// kernel's launch overlaps the FFMA mainloop.)
// ---------------------------------------------------------------------------
__global__ void __launch_bounds__(256, 1) sim_kernel(const float* __restrict__ q,
                                                     const float* __restrict__ feats) {
    extern __shared__ float sm[];
    float* qs = sm;                          // [256][68]  qs[k*68 + qrow]
    float* fs = sm + QS_FLOATS;              // [256][36]  fs[k*36 + frow]
    unsigned long long* red =
        (unsigned long long*)(sm + QS_FLOATS + FS_FLOATS);   // [64][8]

    const int tid  = threadIdx.x;
    const int lane = tid & 31;
    const int w    = tid >> 5;               // 8 warps
    const int f0   = blockIdx.x * FPB;

    // ---- Stage q transposed: 16 coalesced float4 loads per thread ----
    {
        const float4* q4 = reinterpret_cast<const float4*>(q);
        const int r = tid >> 2;              // 0..63 (warp spans 8 rows x 64B)
        const int c = tid & 3;
        #pragma unroll
        for (int half = 0; half < 2; half++) {
            float4 v[8];
            #pragma unroll
            for (int i = 0; i < 8; i++)
                v[i] = q4[r * 64 + c + 4 * (half * 8 + i)];
            #pragma unroll
            for (int i = 0; i < 8; i++) {
                const int k = 4 * (c + 4 * (half * 8 + i));
                qs[(k + 0) * QS_STRIDE + r] = v[i].x;
                qs[(k + 1) * QS_STRIDE + r] = v[i].y;
                qs[(k + 2) * QS_STRIDE + r] = v[i].z;
                qs[(k + 3) * QS_STRIDE + r] = v[i].w;
            }
        }
    }
    // ---- Stage feature tile transposed: 8 coalesced float4 loads per thread ----
    {
        const float4* f4 =
            reinterpret_cast<const float4*>(feats + (size_t)f0 * DD);
        const int r = tid >> 3;              // 0..31 (warp spans 4 rows x 128B)
        const int c = tid & 7;
        float4 v[8];
        #pragma unroll
        for (int i = 0; i < 8; i++)
            v[i] = f4[r * 64 + c + 8 * i];
        #pragma unroll
        for (int i = 0; i < 8; i++) {
            const int k = 4 * (c + 8 * i);
            fs[(k + 0) * FS_STRIDE + r] = v[i].x;
            fs[(k + 1) * FS_STRIDE + r] = v[i].y;
            fs[(k + 2) * FS_STRIDE + r] = v[i].z;
            fs[(k + 3) * FS_STRIDE + r] = v[i].w;
        }
    }
    __syncthreads();

    // PDL: allow the gather kernel to begin launching now; its
    // cudaGridDependencySynchronize() still waits for this grid's completion.
    cudaTriggerProgrammaticLaunchCompletion();

    float acc[2][4];
    #pragma unroll
    for (int i = 0; i < 2; i++)
        #pragma unroll
        for (int j = 0; j < 4; j++) acc[i][j] = 0.f;

    #pragma unroll 8
    for (int k = 0; k < DD; k++) {
        float2 a = *reinterpret_cast<const float2*>(&qs[k * QS_STRIDE + 2 * lane]);
        float4 b = *reinterpret_cast<const float4*>(&fs[k * FS_STRIDE + 4 * w]);
        float bv[4] = {b.x, b.y, b.z, b.w};
        #pragma unroll
        for (int j = 0; j < 4; j++) {
            acc[0][j] = fmaf(a.x, bv[j], acc[0][j]);
            acc[1][j] = fmaf(a.y, bv[j], acc[1][j]);
        }
    }

    // Per-thread max over its 4 features (strict >, ascending j keeps lowest
    // index on tie); one slot per (query row, warp).
    #pragma unroll
    for (int i = 0; i < 2; i++) {
        float m = acc[i][0]; int bj = 0;
        #pragma unroll
        for (int j = 1; j < 4; j++)
            if (acc[i][j] > m) { m = acc[i][j]; bj = j; }
        red[(2 * lane + i) * 8 + w] = packkey(m, (unsigned)(f0 + 4 * w + bj));
    }
    __syncthreads();

    // One thread per query reduces the 8 warp-partials -> its private slot.
    if (tid < NQ) {
        unsigned long long p = red[tid * 8];
        #pragma unroll
        for (int j = 1; j < 8; j++) p = umax64(p, red[tid * 8 + j]);
        g_part[tid * FBLOCKS + blockIdx.x] = p;
    }
}

// ---------------------------------------------------------------------------
// Kernel 2: per-query final argmax reduce + image gather + score write.
// (Exact best-measured copy config: R6/R11. New: launched with PDL; blocks
// come up during sim's mainloop and block in cudaGridDependencySynchronize()
// until sim's g_part writes are visible.)
// ---------------------------------------------------------------------------
__global__ void __launch_bounds__(256, 8) gather_kernel(const float* __restrict__ q,
                                                        const float* __restrict__ images,
                                                        float* __restrict__ out) {
    __shared__ unsigned long long sred[4];
    __shared__ unsigned long long sbest;

    const int qi = blockIdx.y;
    const int t  = threadIdx.x;

    // Wait for the sim grid (PDL edge) before touching g_part.
    cudaGridDependencySynchronize();

    // Reduce 128 per-f-tile partials for this query.
    unsigned long long p = 0ull;
    if (t < FBLOCKS) p = g_part[qi * FBLOCKS + t];
    #pragma unroll
    for (int o = 16; o; o >>= 1)
        p = umax64(p, __shfl_xor_sync(0xffffffffu, p, o));
    if (t < FBLOCKS && (t & 31) == 0) sred[t >> 5] = p;
    __syncthreads();
    if (t == 0) {
        unsigned long long m = sred[0];
        #pragma unroll
        for (int j = 1; j < 4; j++) m = umax64(m, sred[j]);
        sbest = m;
    }
    __syncthreads();

    const unsigned long long best = sbest;
    const unsigned idx = 0xFFFFFFFFu - (unsigned)(best & 0xFFFFFFFFu);

    // Streaming copy of the selected image chunk (loads batched for MLP).
    const float4* src = reinterpret_cast<const float4*>(images + (size_t)idx * IMG)
                        + blockIdx.x * 1024;
    float4* dst = reinterpret_cast<float4*>(out + (size_t)qi * IMG)
                  + blockIdx.x * 1024;
    float4 v[4];
    #pragma unroll
    for (int r = 0; r < 4; r++) v[r] = src[t + 256 * r];
    #pragma unroll
    for (int r = 0; r < 4; r++) dst[t + 256 * r] = v[r];

    // Block (0, qi): compute ||q_qi|| with warp 0 and write normalized score.
    if (blockIdx.x == 0 && t < 32) {
        const float4* qr = reinterpret_cast<const float4*>(q + qi * DD);
        float s = 0.f;
        #pragma unroll
        for (int j = 0; j < 2; j++) {
            float4 w2 = qr[t + 32 * j];
            s += w2.x * w2.x + w2.y * w2.y + w2.z * w2.z + w2.w * w2.w;
        }
        #pragma unroll
        for (int o = 16; o; o >>= 1) s += __shfl_xor_sync(0xffffffffu, s, o);
        if (t == 0) {
            float norm = fmaxf(sqrtf(s), 1e-12f);
            out[(size_t)NQ * IMG + qi] = unpackscore(best) / norm;
        }
    }
}

// ---------------------------------------------------------------------------
extern "C" void kernel_launch(void* const* d_in, const int* in_sizes, int n_in,
                              void* d_out, int out_size) {
    const float* q      = (const float*)d_in[0];   // (64, 256)
    const float* feats  = (const float*)d_in[1];   // (4096, 256), pre-normalized
    const float* images = (const float*)d_in[2];   // (4096, 1, 256, 256)
    float* out = (float*)d_out;                    // 64*65536 imgs + 64 scores

    cudaFuncSetAttribute(sim_kernel,
                         cudaFuncAttributeMaxDynamicSharedMemorySize, SMEM_BYTES);

    sim_kernel<<<FBLOCKS, 256, SMEM_BYTES>>>(q, feats);

    // Gather launched with Programmatic Dependent Launch: starts coming up
    // while sim runs; gridDepSync inside gates the g_part consumption.
    cudaLaunchConfig_t cfg = {};
    cfg.gridDim  = dim3(16, NQ);
    cfg.blockDim = dim3(256);
    cfg.dynamicSmemBytes = 0;
    cfg.stream = 0;
    cudaLaunchAttribute attr[1];
    attr[0].id = cudaLaunchAttributeProgrammaticStreamSerialization;
    attr[0].val.programmaticStreamSerializationAllowed = 1;
    cfg.attrs = attr;
    cfg.numAttrs = 1;
    cudaLaunchKernelEx(&cfg, gather_kernel, q, images, out);
}